// round 2
// baseline (speedup 1.0000x reference)
#include <cuda_runtime.h>
#include <cuda_bf16.h>

// GATConv (PyG default, add self-loops), fp32.
// N=100000, D=128, H=8, C=16, E=800000, Etot=900000.
//
// edge_index dtype is detected at runtime (int64 vs int32 — JAX x64-disabled
// silently downcasts jnp.int64 to int32).

#define NN 100000
#define DD 128
#define HH 8
#define CC 16
#define EE 800000
#define ETOT 900000          // EE + NN

// ---------------- device scratch (allocation-free rule: __device__ globals) ----
__device__ float g_h[NN * DD];      // 51.2 MB
__device__ float g_as[NN * HH];
__device__ float g_ad[NN * HH];
__device__ float g_den[NN * HH];
__device__ int   g_is64;

// ---------------- dtype detect -------------------------------------------------
__global__ void k_detect(const void* __restrict__ ei) {
    const long long* p64 = (const long long*)ei;
    bool ok64 = true;
    for (int i = 0; i < 256; i++) {
        long long v = p64[i];
        if (v < 0 || v >= NN) { ok64 = false; break; }
    }
    g_is64 = ok64 ? 1 : 0;
}

// ---------------- init: denom=0, out=bias --------------------------------------
__global__ void k_init(float* __restrict__ out, const float* __restrict__ bias,
                       int outGuard) {
    int tid = blockIdx.x * blockDim.x + threadIdx.x;
    if (tid < NN * HH) g_den[tid] = 0.0f;
    if (tid < outGuard) out[tid] = bias[tid & (DD - 1)];
}

// ---------------- GEMM: h = x @ W  (M=100000, N=128, K=128) --------------------
__global__ __launch_bounds__(256, 2) void k_gemm(const float* __restrict__ x,
                                                 const float* __restrict__ W) {
    __shared__ float Xs[128][33];
    __shared__ float Ws[32][128];
    const int tid = threadIdx.x;
    const int tx = tid & 15;
    const int ty = tid >> 4;
    const int rowBase = blockIdx.x * 128;

    float acc[8][8];
#pragma unroll
    for (int i = 0; i < 8; i++)
#pragma unroll
        for (int j = 0; j < 8; j++) acc[i][j] = 0.0f;

    for (int k0 = 0; k0 < 128; k0 += 32) {
        for (int i = tid; i < 1024; i += 256) {
            int r = i >> 3;
            int k4 = i & 7;
            float4 v = make_float4(0.f, 0.f, 0.f, 0.f);
            int gr = rowBase + r;
            if (gr < NN) v = *(const float4*)(x + (size_t)gr * DD + k0 + k4 * 4);
            Xs[r][k4 * 4 + 0] = v.x; Xs[r][k4 * 4 + 1] = v.y;
            Xs[r][k4 * 4 + 2] = v.z; Xs[r][k4 * 4 + 3] = v.w;
        }
        for (int i = tid; i < 1024; i += 256) {
            int kk = i >> 5;
            int c4 = i & 31;
            *(float4*)(&Ws[kk][c4 * 4]) = *(const float4*)(W + (size_t)(k0 + kk) * DD + c4 * 4);
        }
        __syncthreads();

#pragma unroll
        for (int kk = 0; kk < 32; kk++) {
            float a[8], b[8];
#pragma unroll
            for (int i = 0; i < 8; i++) a[i] = Xs[ty * 8 + i][kk];
            float4 b0 = *(const float4*)(&Ws[kk][tx * 8]);
            float4 b1 = *(const float4*)(&Ws[kk][tx * 8 + 4]);
            b[0] = b0.x; b[1] = b0.y; b[2] = b0.z; b[3] = b0.w;
            b[4] = b1.x; b[5] = b1.y; b[6] = b1.z; b[7] = b1.w;
#pragma unroll
            for (int i = 0; i < 8; i++)
#pragma unroll
                for (int j = 0; j < 8; j++) acc[i][j] = fmaf(a[i], b[j], acc[i][j]);
        }
        __syncthreads();
    }

#pragma unroll
    for (int i = 0; i < 8; i++) {
        int gr = rowBase + ty * 8 + i;
        if (gr < NN) {
            float4 v0 = make_float4(acc[i][0], acc[i][1], acc[i][2], acc[i][3]);
            float4 v1 = make_float4(acc[i][4], acc[i][5], acc[i][6], acc[i][7]);
            *(float4*)(g_h + (size_t)gr * DD + tx * 8)     = v0;
            *(float4*)(g_h + (size_t)gr * DD + tx * 8 + 4) = v1;
        }
    }
}

// ---------------- per-(node,head) attention dots -------------------------------
__global__ void k_attn(const float* __restrict__ att_src, const float* __restrict__ att_dst) {
    int tid = blockIdx.x * blockDim.x + threadIdx.x;
    if (tid >= NN * HH) return;
    int n = tid >> 3;
    int h = tid & 7;
    const float4* hp = (const float4*)(g_h + (size_t)n * DD + h * CC);
    const float4* sp = (const float4*)(att_src + h * CC);
    const float4* dp = (const float4*)(att_dst + h * CC);
    float ssum = 0.f, dsum = 0.f;
#pragma unroll
    for (int i = 0; i < 4; i++) {
        float4 hv = hp[i], sv = sp[i], dv = dp[i];
        ssum += hv.x * sv.x + hv.y * sv.y + hv.z * sv.z + hv.w * sv.w;
        dsum += hv.x * dv.x + hv.y * dv.y + hv.z * dv.z + hv.w * dv.w;
    }
    g_as[tid] = ssum;
    g_ad[tid] = dsum;
}

// ---------------- edge decode (dtype-aware) ------------------------------------
__device__ __forceinline__ bool edge_src_dst(const void* __restrict__ ei, int e,
                                             int& src, int& dst) {
    if (e >= EE) { src = dst = e - EE; return true; }   // self-loop
    if (g_is64) {
        src = (int)((const long long*)ei)[e];
        dst = (int)((const long long*)ei)[EE + e];
    } else {
        src = ((const int*)ei)[e];
        dst = ((const int*)ei)[EE + e];
    }
    return (unsigned)src < NN && (unsigned)dst < NN;
}

// ---------------- edge pass 1: softmax denominators ----------------------------
__global__ void k_denom(const void* __restrict__ ei) {
    int tid = blockIdx.x * blockDim.x + threadIdx.x;
    if (tid >= ETOT * HH) return;
    int e = tid >> 3;
    int h = tid & 7;
    int src, dst;
    if (!edge_src_dst(ei, e, src, dst)) return;
    float l = g_as[src * HH + h] + g_ad[dst * HH + h];
    l = l > 0.f ? l : 0.2f * l;
    atomicAdd(&g_den[dst * HH + h], expf(l));
}

// ---------------- edge pass 2: alpha + message scatter -------------------------
__device__ __forceinline__ void red_add_v4(float* p, float a, float b, float c, float d) {
    asm volatile("red.global.add.v4.f32 [%0], {%1,%2,%3,%4};"
                 :: "l"(p), "f"(a), "f"(b), "f"(c), "f"(d) : "memory");
}

__global__ void k_scatter(const void* __restrict__ ei, float* __restrict__ out,
                          float* __restrict__ alphaOut) {
    int tid = blockIdx.x * blockDim.x + threadIdx.x;
    if (tid >= ETOT * HH) return;
    int e = tid >> 3;
    int h = tid & 7;
    int src, dst;
    if (!edge_src_dst(ei, e, src, dst)) return;
    float l = g_as[src * HH + h] + g_ad[dst * HH + h];
    l = l > 0.f ? l : 0.2f * l;
    float ex = expf(l);
    float alpha = ex / (g_den[dst * HH + h] + 1e-16f);
    if (alphaOut) alphaOut[tid] = alpha;

    const float4* hp = (const float4*)(g_h + (size_t)src * DD + h * CC);
    float* op = out + (size_t)dst * DD + h * CC;
#pragma unroll
    for (int i = 0; i < 4; i++) {
        float4 v = hp[i];
        red_add_v4(op + i * 4, v.x * alpha, v.y * alpha, v.z * alpha, v.w * alpha);
    }
}

// ---------------- optional ei output section -----------------------------------
__global__ void k_ei_f32(const void* __restrict__ ei, float* __restrict__ o) {
    int tid = blockIdx.x * blockDim.x + threadIdx.x;
    if (tid >= 2 * ETOT) return;
    int row = tid / ETOT;
    int i = tid - row * ETOT;
    long long v;
    if (i < EE) {
        v = g_is64 ? ((const long long*)ei)[(size_t)row * EE + i]
                   : (long long)((const int*)ei)[(size_t)row * EE + i];
    } else {
        v = (long long)(i - EE);
    }
    o[tid] = (float)v;
}

__global__ void k_ei_i64(const void* __restrict__ ei, long long* __restrict__ o) {
    int tid = blockIdx.x * blockDim.x + threadIdx.x;
    if (tid >= 2 * ETOT) return;
    int row = tid / ETOT;
    int i = tid - row * ETOT;
    long long v;
    if (i < EE) {
        v = g_is64 ? ((const long long*)ei)[(size_t)row * EE + i]
                   : (long long)((const int*)ei)[(size_t)row * EE + i];
    } else {
        v = (long long)(i - EE);
    }
    o[tid] = v;
}

// ---------------- launch --------------------------------------------------------
extern "C" void kernel_launch(void* const* d_in, const int* in_sizes, int n_in,
                              void* d_out, int out_size) {
    const float* x       = (const float*)d_in[0];
    const void*  ei      = d_in[1];
    const float* W       = (const float*)d_in[2];
    const float* att_src = (const float*)d_in[3];
    const float* att_dst = (const float*)d_in[4];
    const float* bias    = (const float*)d_in[5];
    float* out = (float*)d_out;

    const int OUTN = NN * DD;        // 12,800,000
    const int EIN  = 2 * ETOT;       //  1,800,000
    const int ALPH = ETOT * HH;      //  7,200,000

    float* alphaOut = nullptr;
    int    eiMode   = 0;             // 0 none, 1 float32, 2 int64
    if (out_size == OUTN + ALPH) {
        alphaOut = out + OUTN;
    } else if (out_size == OUTN + EIN + ALPH) {
        eiMode = 1;
        alphaOut = out + OUTN + EIN;
    } else if (out_size == OUTN + 2 * EIN + ALPH) {
        eiMode = 2;
        alphaOut = out + OUTN + 2 * EIN;
    }

    int outGuard = out_size < OUTN ? out_size : OUTN;

    k_detect<<<1, 1>>>(ei);
    k_init<<<(OUTN + 255) / 256, 256>>>(out, bias, outGuard);
    k_gemm<<<(NN + 127) / 128, 256>>>(x, W);
    k_attn<<<(NN * HH + 255) / 256, 256>>>(att_src, att_dst);
    k_denom<<<(ETOT * HH + 255) / 256, 256>>>(ei);
    k_scatter<<<(ETOT * HH + 255) / 256, 256>>>(ei, out, alphaOut);
    if (eiMode == 1) {
        k_ei_f32<<<(2 * ETOT + 255) / 256, 256>>>(ei, out + OUTN);
    } else if (eiMode == 2) {
        k_ei_i64<<<(2 * ETOT + 255) / 256, 256>>>(ei, (long long*)(out + OUTN));
    }
}

// round 4
// speedup vs baseline: 2.0096x; 2.0096x over previous
#include <cuda_runtime.h>
#include <cuda_bf16.h>

// GATConv (PyG default, add self-loops), fp32.  N=100000, D=128, H=8, C=16,
// E=800000, Etot=900000.
//
// R4: fix k_agg grid (one warp per node => NN*32 threads; R3 launched 1/4 of
// the warps, leaving 75% of out poisoned -> rel_err sqrt(0.75)=0.866).

#define NN 100000
#define DD 128
#define HH 8
#define CC 16
#define EE 800000
#define ETOT 900000          // EE + NN
#define NB  ((NN + 255) / 256)   // 391 scan blocks

// ---------------- device scratch ----------------------------------------------
__device__ float g_h[NN * DD];          // 51.2 MB
__device__ float g_as[NN * HH];
__device__ float g_ad[NN * HH];
__device__ int   g_cnt[NN];             // degree (incl self-loop)
__device__ int   g_loc[NN];             // block-local exclusive scan
__device__ int   g_bsum[NB];            // per-block sums
__device__ int   g_off[NN + 1];         // CSR offsets
__device__ int   g_cur[NN];             // fill cursors
__device__ int   g_srcList[ETOT];
__device__ int   g_eidList[ETOT];
__device__ int   g_is64;

// ---------------- dtype detect -------------------------------------------------
__global__ void k_detect(const void* __restrict__ ei) {
    const long long* p64 = (const long long*)ei;
    bool ok64 = true;
    for (int i = 0; i < 256; i++) {
        long long v = p64[i];
        if (v < 0 || v >= NN) { ok64 = false; break; }
    }
    g_is64 = ok64 ? 1 : 0;
}

// ---------------- edge decode (dtype-aware) ------------------------------------
__device__ __forceinline__ bool edge_src_dst(const void* __restrict__ ei, int e,
                                             int& src, int& dst) {
    if (e >= EE) { src = dst = e - EE; return true; }   // self-loop
    if (g_is64) {
        src = (int)((const long long*)ei)[e];
        dst = (int)((const long long*)ei)[EE + e];
    } else {
        src = ((const int*)ei)[e];
        dst = ((const int*)ei)[EE + e];
    }
    return (unsigned)src < NN && (unsigned)dst < NN;
}

// ---------------- CSR build -----------------------------------------------------
__global__ void k_cnt_init() {           // cnt = 1 (self-loop pre-counted)
    int i = blockIdx.x * blockDim.x + threadIdx.x;
    if (i < NN) g_cnt[i] = 1;
}

__global__ void k_hist(const void* __restrict__ ei) {
    int e = blockIdx.x * blockDim.x + threadIdx.x;
    if (e >= EE) return;
    int src, dst;
    if (!edge_src_dst(ei, e, src, dst)) return;
    atomicAdd(&g_cnt[dst], 1);
}

__global__ void k_scan1() {
    __shared__ int s[256];
    int t = threadIdx.x;
    int i = blockIdx.x * 256 + t;
    int v = (i < NN) ? g_cnt[i] : 0;
    s[t] = v;
    __syncthreads();
#pragma unroll
    for (int d = 1; d < 256; d <<= 1) {
        int add = (t >= d) ? s[t - d] : 0;
        __syncthreads();
        s[t] += add;
        __syncthreads();
    }
    if (i < NN) g_loc[i] = s[t] - v;
    if (t == 255) g_bsum[blockIdx.x] = s[255];
}

__global__ void k_scan2() {              // single block, 512 threads >= NB
    __shared__ int s[512];
    int t = threadIdx.x;
    int v = (t < NB) ? g_bsum[t] : 0;
    s[t] = v;
    __syncthreads();
#pragma unroll
    for (int d = 1; d < 512; d <<= 1) {
        int add = (t >= d) ? s[t - d] : 0;
        __syncthreads();
        s[t] += add;
        __syncthreads();
    }
    if (t < NB) g_bsum[t] = s[t] - v;    // exclusive
}

__global__ void k_scan3() {
    int i = blockIdx.x * blockDim.x + threadIdx.x;
    if (i < NN) {
        int o = g_loc[i] + g_bsum[i >> 8];
        g_off[i] = o;
        g_cur[i] = o;
    }
    if (i == 0) g_off[NN] = ETOT;
}

__global__ void k_fill(const void* __restrict__ ei) {
    int e = blockIdx.x * blockDim.x + threadIdx.x;
    if (e >= ETOT) return;
    int src, dst;
    if (!edge_src_dst(ei, e, src, dst)) return;
    int pos = atomicAdd(&g_cur[dst], 1);
    g_srcList[pos] = src;
    g_eidList[pos] = e;
}

// ---------------- GEMM: h = x @ W, fused attn dots -----------------------------
// 128x128 tile, 256 threads, 8x8 micro-tile as f32x2 pairs.
__device__ __forceinline__ unsigned long long pack2(float lo, float hi) {
    unsigned long long r;
    asm("mov.b64 %0, {%1, %2};" : "=l"(r) : "f"(lo), "f"(hi));
    return r;
}
__device__ __forceinline__ void unpack2(unsigned long long p, float& lo, float& hi) {
    asm("mov.b64 {%0, %1}, %2;" : "=f"(lo), "=f"(hi) : "l"(p));
}
__device__ __forceinline__ void fma2(unsigned long long& d, unsigned long long a,
                                     unsigned long long b) {
    asm("fma.rn.f32x2 %0, %1, %2, %0;" : "+l"(d) : "l"(a), "l"(b));
}

__global__ __launch_bounds__(256, 2) void k_gemm(const float* __restrict__ x,
                                                 const float* __restrict__ W,
                                                 const float* __restrict__ att_src,
                                                 const float* __restrict__ att_dst) {
    __shared__ float Xs[128][33];
    __shared__ float Ws[32][128];
    const int tid = threadIdx.x;
    const int tx = tid & 15;
    const int ty = tid >> 4;
    const int rowBase = blockIdx.x * 128;

    unsigned long long acc[8][4];
#pragma unroll
    for (int i = 0; i < 8; i++)
#pragma unroll
        for (int j = 0; j < 4; j++) acc[i][j] = 0ull;

    for (int k0 = 0; k0 < 128; k0 += 32) {
        for (int i = tid; i < 1024; i += 256) {
            int r = i >> 3;
            int k4 = i & 7;
            float4 v = make_float4(0.f, 0.f, 0.f, 0.f);
            int gr = rowBase + r;
            if (gr < NN) v = *(const float4*)(x + (size_t)gr * DD + k0 + k4 * 4);
            Xs[r][k4 * 4 + 0] = v.x; Xs[r][k4 * 4 + 1] = v.y;
            Xs[r][k4 * 4 + 2] = v.z; Xs[r][k4 * 4 + 3] = v.w;
        }
        for (int i = tid; i < 1024; i += 256) {
            int kk = i >> 5;
            int c4 = i & 31;
            *(float4*)(&Ws[kk][c4 * 4]) = *(const float4*)(W + (size_t)(k0 + kk) * DD + c4 * 4);
        }
        __syncthreads();

#pragma unroll
        for (int kk = 0; kk < 32; kk++) {
            float4 b0 = *(const float4*)(&Ws[kk][tx * 8]);
            float4 b1 = *(const float4*)(&Ws[kk][tx * 8 + 4]);
            unsigned long long bp[4];
            bp[0] = pack2(b0.x, b0.y);
            bp[1] = pack2(b0.z, b0.w);
            bp[2] = pack2(b1.x, b1.y);
            bp[3] = pack2(b1.z, b1.w);
#pragma unroll
            for (int i = 0; i < 8; i++) {
                float a = Xs[ty * 8 + i][kk];
                unsigned long long ap = pack2(a, a);
#pragma unroll
                for (int j = 0; j < 4; j++) fma2(acc[i][j], ap, bp[j]);
            }
        }
        __syncthreads();
    }

    // attn vectors for this thread's 8 columns (all in head tx/2)
    const int head = tx >> 1;
    const int cbase = head * CC + (tx & 1) * 8;
    float4 as0 = *(const float4*)(att_src + cbase);
    float4 as1 = *(const float4*)(att_src + cbase + 4);
    float4 ad0 = *(const float4*)(att_dst + cbase);
    float4 ad1 = *(const float4*)(att_dst + cbase + 4);
    float av[8] = {as0.x, as0.y, as0.z, as0.w, as1.x, as1.y, as1.z, as1.w};
    float dv[8] = {ad0.x, ad0.y, ad0.z, ad0.w, ad1.x, ad1.y, ad1.z, ad1.w};

#pragma unroll
    for (int i = 0; i < 8; i++) {
        int gr = rowBase + ty * 8 + i;
        float c[8];
        unpack2(acc[i][0], c[0], c[1]);
        unpack2(acc[i][1], c[2], c[3]);
        unpack2(acc[i][2], c[4], c[5]);
        unpack2(acc[i][3], c[6], c[7]);
        if (gr < NN) {
            *(float4*)(g_h + (size_t)gr * DD + tx * 8)     = make_float4(c[0], c[1], c[2], c[3]);
            *(float4*)(g_h + (size_t)gr * DD + tx * 8 + 4) = make_float4(c[4], c[5], c[6], c[7]);
        }
        float ssum = 0.f, dsum = 0.f;
#pragma unroll
        for (int j = 0; j < 8; j++) {
            ssum = fmaf(c[j], av[j], ssum);
            dsum = fmaf(c[j], dv[j], dsum);
        }
        // combine the two half-head threads (lanes tx, tx^1 are adjacent)
        ssum += __shfl_xor_sync(0xFFFFFFFFu, ssum, 1);
        dsum += __shfl_xor_sync(0xFFFFFFFFu, dsum, 1);
        if (((tx & 1) == 0) && gr < NN) {
            g_as[gr * HH + head] = ssum;
            g_ad[gr * HH + head] = dsum;
        }
    }
}

// ---------------- aggregation: one warp per dst node ----------------------------
__global__ __launch_bounds__(256) void k_agg(float* __restrict__ out,
                                             float* __restrict__ alphaOut,
                                             const float* __restrict__ bias) {
    int warpId = (blockIdx.x * blockDim.x + threadIdx.x) >> 5;
    int lane = threadIdx.x & 31;
    if (warpId >= NN) return;
    const int n = warpId;
    const int beg = g_off[n], end = g_off[n + 1];

    float ad = (lane < HH) ? g_ad[n * HH + lane] : 0.f;
    float denom = 0.f;
    float acc0 = 0.f, acc1 = 0.f, acc2 = 0.f, acc3 = 0.f;
    const int hsel = lane >> 4;          // 0 or 1

    for (int p = beg; p < end; p++) {
        int src = g_srcList[p];
        float ex = 0.f;
        if (lane < HH) {
            float l = g_as[src * HH + lane] + ad;
            l = l > 0.f ? l : 0.2f * l;
            ex = __expf(l);
            denom += ex;
        }
        float e0 = __shfl_sync(0xFFFFFFFFu, ex, hsel);
        float e1 = __shfl_sync(0xFFFFFFFFu, ex, 2 + hsel);
        float e2 = __shfl_sync(0xFFFFFFFFu, ex, 4 + hsel);
        float e3 = __shfl_sync(0xFFFFFFFFu, ex, 6 + hsel);
        const float* hp = g_h + (size_t)src * DD;
        acc0 = fmaf(e0, hp[lane],      acc0);
        acc1 = fmaf(e1, hp[lane + 32], acc1);
        acc2 = fmaf(e2, hp[lane + 64], acc2);
        acc3 = fmaf(e3, hp[lane + 96], acc3);
    }

    float dinv = (lane < HH) ? 1.f / (denom + 1e-16f) : 0.f;
    float d0 = __shfl_sync(0xFFFFFFFFu, dinv, hsel);
    float d1 = __shfl_sync(0xFFFFFFFFu, dinv, 2 + hsel);
    float d2 = __shfl_sync(0xFFFFFFFFu, dinv, 4 + hsel);
    float d3 = __shfl_sync(0xFFFFFFFFu, dinv, 6 + hsel);

    float* op = out + (size_t)n * DD;
    op[lane]      = acc0 * d0 + bias[lane];
    op[lane + 32] = acc1 * d1 + bias[lane + 32];
    op[lane + 64] = acc2 * d2 + bias[lane + 64];
    op[lane + 96] = acc3 * d3 + bias[lane + 96];

    if (alphaOut) {
        for (int p = beg; p < end; p++) {
            if (lane < HH) {
                int src = g_srcList[p];
                int eid = g_eidList[p];
                float l = g_as[src * HH + lane] + ad;
                l = l > 0.f ? l : 0.2f * l;
                alphaOut[(size_t)eid * HH + lane] = __expf(l) * dinv;
            }
        }
    }
}

// ---------------- optional ei output section -----------------------------------
__global__ void k_ei_f32(const void* __restrict__ ei, float* __restrict__ o) {
    int tid = blockIdx.x * blockDim.x + threadIdx.x;
    if (tid >= 2 * ETOT) return;
    int row = tid / ETOT;
    int i = tid - row * ETOT;
    long long v;
    if (i < EE) {
        v = g_is64 ? ((const long long*)ei)[(size_t)row * EE + i]
                   : (long long)((const int*)ei)[(size_t)row * EE + i];
    } else {
        v = (long long)(i - EE);
    }
    o[tid] = (float)v;
}

__global__ void k_ei_i64(const void* __restrict__ ei, long long* __restrict__ o) {
    int tid = blockIdx.x * blockDim.x + threadIdx.x;
    if (tid >= 2 * ETOT) return;
    int row = tid / ETOT;
    int i = tid - row * ETOT;
    long long v;
    if (i < EE) {
        v = g_is64 ? ((const long long*)ei)[(size_t)row * EE + i]
                   : (long long)((const int*)ei)[(size_t)row * EE + i];
    } else {
        v = (long long)(i - EE);
    }
    o[tid] = v;
}

// ---------------- launch --------------------------------------------------------
extern "C" void kernel_launch(void* const* d_in, const int* in_sizes, int n_in,
                              void* d_out, int out_size) {
    const float* x       = (const float*)d_in[0];
    const void*  ei      = d_in[1];
    const float* W       = (const float*)d_in[2];
    const float* att_src = (const float*)d_in[3];
    const float* att_dst = (const float*)d_in[4];
    const float* bias    = (const float*)d_in[5];
    float* out = (float*)d_out;

    const int OUTN = NN * DD;        // 12,800,000
    const int EIN  = 2 * ETOT;       //  1,800,000
    const int ALPH = ETOT * HH;      //  7,200,000

    float* alphaOut = nullptr;
    int    eiMode   = 0;             // 0 none, 1 float32, 2 int64
    if (out_size == OUTN + ALPH) {
        alphaOut = out + OUTN;
    } else if (out_size == OUTN + EIN + ALPH) {
        eiMode = 1;
        alphaOut = out + OUTN + EIN;
    } else if (out_size == OUTN + 2 * EIN + ALPH) {
        eiMode = 2;
        alphaOut = out + OUTN + 2 * EIN;
    }

    k_detect<<<1, 1>>>(ei);
    k_cnt_init<<<NB, 256>>>();
    k_hist<<<(EE + 255) / 256, 256>>>(ei);
    k_scan1<<<NB, 256>>>();
    k_scan2<<<1, 512>>>();
    k_scan3<<<NB, 256>>>();
    k_fill<<<(ETOT + 255) / 256, 256>>>(ei);
    k_gemm<<<(NN + 127) / 128, 256>>>(x, W, att_src, att_dst);
    // one warp per node: NN*32 threads total
    k_agg<<<(NN * 32 + 255) / 256, 256>>>(out, alphaOut, bias);
    if (eiMode == 1) {
        k_ei_f32<<<(2 * ETOT + 255) / 256, 256>>>(ei, out + OUTN);
    } else if (eiMode == 2) {
        k_ei_i64<<<(2 * ETOT + 255) / 256, 256>>>(ei, (long long*)(out + OUTN));
    }
}

// round 11
// speedup vs baseline: 2.2593x; 1.1243x over previous
#include <cuda_runtime.h>
#include <cuda_bf16.h>

// GATConv (PyG default, add self-loops), fp32.  N=100000, D=128, H=8, C=16,
// E=800000, Etot=900000.
//
// R6: fix cp.async misalignment (Xs row stride 68B -> 80B, 16B-aligned).
// Otherwise identical to R5: cp.async double-buffered GEMM (KC=16), f32x2
// micro-tile, fused attn epilogue, warp-per-node CSR aggregation (x2 unroll).

#define NN 100000
#define DD 128
#define HH 8
#define CC 16
#define EE 800000
#define ETOT 900000          // EE + NN
#define NB  ((NN + 255) / 256)   // 391 scan blocks

// ---------------- device scratch ----------------------------------------------
__device__ float g_h[NN * DD];          // 51.2 MB
__device__ float g_as[NN * HH];
__device__ float g_ad[NN * HH];
__device__ int   g_cnt[NN];
__device__ int   g_loc[NN];
__device__ int   g_bsum[NB];
__device__ int   g_off[NN + 1];
__device__ int   g_cur[NN];
__device__ int   g_srcList[ETOT];
__device__ int   g_eidList[ETOT];
__device__ int   g_is64;

// ---------------- dtype detect -------------------------------------------------
__global__ void k_detect(const void* __restrict__ ei) {
    const long long* p64 = (const long long*)ei;
    bool ok64 = true;
    for (int i = 0; i < 256; i++) {
        long long v = p64[i];
        if (v < 0 || v >= NN) { ok64 = false; break; }
    }
    g_is64 = ok64 ? 1 : 0;
}

// ---------------- edge decode (dtype-aware) ------------------------------------
__device__ __forceinline__ bool edge_src_dst(const void* __restrict__ ei, int e,
                                             int& src, int& dst) {
    if (e >= EE) { src = dst = e - EE; return true; }   // self-loop
    if (g_is64) {
        src = (int)((const long long*)ei)[e];
        dst = (int)((const long long*)ei)[EE + e];
    } else {
        src = ((const int*)ei)[e];
        dst = ((const int*)ei)[EE + e];
    }
    return (unsigned)src < NN && (unsigned)dst < NN;
}

// ---------------- CSR build -----------------------------------------------------
__global__ void k_cnt_init() {
    int i = blockIdx.x * blockDim.x + threadIdx.x;
    if (i < NN) g_cnt[i] = 1;
}

__global__ void k_hist(const void* __restrict__ ei) {
    int e = blockIdx.x * blockDim.x + threadIdx.x;
    if (e >= EE) return;
    int src, dst;
    if (!edge_src_dst(ei, e, src, dst)) return;
    atomicAdd(&g_cnt[dst], 1);
}

__global__ void k_scan1() {
    __shared__ int s[256];
    int t = threadIdx.x;
    int i = blockIdx.x * 256 + t;
    int v = (i < NN) ? g_cnt[i] : 0;
    s[t] = v;
    __syncthreads();
#pragma unroll
    for (int d = 1; d < 256; d <<= 1) {
        int add = (t >= d) ? s[t - d] : 0;
        __syncthreads();
        s[t] += add;
        __syncthreads();
    }
    if (i < NN) g_loc[i] = s[t] - v;
    if (t == 255) g_bsum[blockIdx.x] = s[255];
}

__global__ void k_scan2() {
    __shared__ int s[512];
    int t = threadIdx.x;
    int v = (t < NB) ? g_bsum[t] : 0;
    s[t] = v;
    __syncthreads();
#pragma unroll
    for (int d = 1; d < 512; d <<= 1) {
        int add = (t >= d) ? s[t - d] : 0;
        __syncthreads();
        s[t] += add;
        __syncthreads();
    }
    if (t < NB) g_bsum[t] = s[t] - v;
}

__global__ void k_scan3() {
    int i = blockIdx.x * blockDim.x + threadIdx.x;
    if (i < NN) {
        int o = g_loc[i] + g_bsum[i >> 8];
        g_off[i] = o;
        g_cur[i] = o;
    }
    if (i == 0) g_off[NN] = ETOT;
}

__global__ void k_fill(const void* __restrict__ ei) {
    int e = blockIdx.x * blockDim.x + threadIdx.x;
    if (e >= ETOT) return;
    int src, dst;
    if (!edge_src_dst(ei, e, src, dst)) return;
    int pos = atomicAdd(&g_cur[dst], 1);
    g_srcList[pos] = src;
    g_eidList[pos] = e;
}

// ---------------- f32x2 helpers -------------------------------------------------
__device__ __forceinline__ unsigned long long pack2(float lo, float hi) {
    unsigned long long r;
    asm("mov.b64 %0, {%1, %2};" : "=l"(r) : "f"(lo), "f"(hi));
    return r;
}
__device__ __forceinline__ void unpack2(unsigned long long p, float& lo, float& hi) {
    asm("mov.b64 {%0, %1}, %2;" : "=f"(lo), "=f"(hi) : "l"(p));
}
__device__ __forceinline__ void fma2(unsigned long long& d, unsigned long long a,
                                     unsigned long long b) {
    asm("fma.rn.f32x2 %0, %1, %2, %0;" : "+l"(d) : "l"(a), "l"(b));
}

// ---------------- cp.async helpers ----------------------------------------------
__device__ __forceinline__ void cp16(void* smem_dst, const void* gsrc, int bytes) {
    unsigned int d = (unsigned int)__cvta_generic_to_shared(smem_dst);
    asm volatile("cp.async.ca.shared.global [%0], [%1], 16, %2;"
                 :: "r"(d), "l"(gsrc), "r"(bytes));
}
__device__ __forceinline__ void cp_commit() {
    asm volatile("cp.async.commit_group;");
}
template <int Ngroups>
__device__ __forceinline__ void cp_wait() {
    asm volatile("cp.async.wait_group %0;" :: "n"(Ngroups));
}

// ---------------- GEMM: h = x @ W, fused attn dots -----------------------------
// 128x128 tile, 256 threads, 8x8 f32x2 micro-tile, cp.async double buffer, KC=16.
#define KC 16
#define XPAD 20   // floats per Xs row: 80 bytes, 16B-aligned for cp.async

__global__ __launch_bounds__(256, 2) void k_gemm(const float* __restrict__ x,
                                                 const float* __restrict__ W,
                                                 const float* __restrict__ att_src,
                                                 const float* __restrict__ att_dst) {
    __shared__ float Xs[2][128][XPAD];
    __shared__ float Ws[2][KC][128];
    const int tid = threadIdx.x;
    const int tx = tid & 15;
    const int ty = tid >> 4;
    const int rowBase = blockIdx.x * 128;

    unsigned long long acc[8][4];
#pragma unroll
    for (int i = 0; i < 8; i++)
#pragma unroll
        for (int j = 0; j < 4; j++) acc[i][j] = 0ull;

    // stage(k0, buf): 512 cp.async for Xs (128 rows x 4 float4) + 512 for Ws
    auto stage = [&](int k0, int buf) {
#pragma unroll
        for (int i = tid; i < 512; i += 256) {
            int r = i >> 2;
            int k4 = i & 3;
            int gr = rowBase + r;
            cp16(&Xs[buf][r][k4 * 4],
                 x + (size_t)(gr < NN ? gr : 0) * DD + k0 + k4 * 4,
                 gr < NN ? 16 : 0);
        }
#pragma unroll
        for (int i = tid; i < 512; i += 256) {
            int kk = i >> 5;
            int c4 = i & 31;
            cp16(&Ws[buf][kk][c4 * 4], W + (size_t)(k0 + kk) * DD + c4 * 4, 16);
        }
        cp_commit();
    };

    stage(0, 0);

#pragma unroll
    for (int it = 0; it < 8; it++) {
        if (it < 7) stage((it + 1) * KC, (it + 1) & 1);
        if (it < 7) cp_wait<1>(); else cp_wait<0>();
        __syncthreads();
        const int b = it & 1;
#pragma unroll
        for (int kk = 0; kk < KC; kk++) {
            float4 b0 = *(const float4*)(&Ws[b][kk][tx * 8]);
            float4 b1 = *(const float4*)(&Ws[b][kk][tx * 8 + 4]);
            unsigned long long bp[4];
            bp[0] = pack2(b0.x, b0.y);
            bp[1] = pack2(b0.z, b0.w);
            bp[2] = pack2(b1.x, b1.y);
            bp[3] = pack2(b1.z, b1.w);
#pragma unroll
            for (int i = 0; i < 8; i++) {
                float a = Xs[b][ty * 8 + i][kk];
                unsigned long long ap = pack2(a, a);
#pragma unroll
                for (int j = 0; j < 4; j++) fma2(acc[i][j], ap, bp[j]);
            }
        }
        __syncthreads();
    }

    // attn vectors for this thread's 8 columns (all in head tx/2)
    const int head = tx >> 1;
    const int cbase = head * CC + (tx & 1) * 8;
    float4 as0 = *(const float4*)(att_src + cbase);
    float4 as1 = *(const float4*)(att_src + cbase + 4);
    float4 ad0 = *(const float4*)(att_dst + cbase);
    float4 ad1 = *(const float4*)(att_dst + cbase + 4);
    float av[8] = {as0.x, as0.y, as0.z, as0.w, as1.x, as1.y, as1.z, as1.w};
    float dv[8] = {ad0.x, ad0.y, ad0.z, ad0.w, ad1.x, ad1.y, ad1.z, ad1.w};

#pragma unroll
    for (int i = 0; i < 8; i++) {
        int gr = rowBase + ty * 8 + i;
        float c[8];
        unpack2(acc[i][0], c[0], c[1]);
        unpack2(acc[i][1], c[2], c[3]);
        unpack2(acc[i][2], c[4], c[5]);
        unpack2(acc[i][3], c[6], c[7]);
        if (gr < NN) {
            *(float4*)(g_h + (size_t)gr * DD + tx * 8)     = make_float4(c[0], c[1], c[2], c[3]);
            *(float4*)(g_h + (size_t)gr * DD + tx * 8 + 4) = make_float4(c[4], c[5], c[6], c[7]);
        }
        float ssum = 0.f, dsum = 0.f;
#pragma unroll
        for (int j = 0; j < 8; j++) {
            ssum = fmaf(c[j], av[j], ssum);
            dsum = fmaf(c[j], dv[j], dsum);
        }
        ssum += __shfl_xor_sync(0xFFFFFFFFu, ssum, 1);
        dsum += __shfl_xor_sync(0xFFFFFFFFu, dsum, 1);
        if (((tx & 1) == 0) && gr < NN) {
            g_as[gr * HH + head] = ssum;
            g_ad[gr * HH + head] = dsum;
        }
    }
}

// ---------------- aggregation: one warp per dst node, unrolled x2 ---------------
__global__ __launch_bounds__(256) void k_agg(float* __restrict__ out,
                                             float* __restrict__ alphaOut,
                                             const float* __restrict__ bias) {
    int warpId = (blockIdx.x * blockDim.x + threadIdx.x) >> 5;
    int lane = threadIdx.x & 31;
    if (warpId >= NN) return;
    const int n = warpId;
    const int beg = g_off[n], end = g_off[n + 1];

    float ad = (lane < HH) ? g_ad[n * HH + lane] : 0.f;
    float denom = 0.f;
    float acc0 = 0.f, acc1 = 0.f, acc2 = 0.f, acc3 = 0.f;
    const int hsel = lane >> 4;          // 0 or 1

    int p = beg;
    for (; p + 1 < end; p += 2) {
        int s0 = g_srcList[p];
        int s1 = g_srcList[p + 1];
        float ex0 = 0.f, ex1 = 0.f;
        if (lane < HH) {
            float l0 = g_as[s0 * HH + lane] + ad;
            float l1 = g_as[s1 * HH + lane] + ad;
            l0 = l0 > 0.f ? l0 : 0.2f * l0;
            l1 = l1 > 0.f ? l1 : 0.2f * l1;
            ex0 = __expf(l0);
            ex1 = __expf(l1);
            denom += ex0 + ex1;
        }
        float e00 = __shfl_sync(0xFFFFFFFFu, ex0, hsel);
        float e01 = __shfl_sync(0xFFFFFFFFu, ex0, 2 + hsel);
        float e02 = __shfl_sync(0xFFFFFFFFu, ex0, 4 + hsel);
        float e03 = __shfl_sync(0xFFFFFFFFu, ex0, 6 + hsel);
        float e10 = __shfl_sync(0xFFFFFFFFu, ex1, hsel);
        float e11 = __shfl_sync(0xFFFFFFFFu, ex1, 2 + hsel);
        float e12 = __shfl_sync(0xFFFFFFFFu, ex1, 4 + hsel);
        float e13 = __shfl_sync(0xFFFFFFFFu, ex1, 6 + hsel);
        const float* h0 = g_h + (size_t)s0 * DD;
        const float* h1 = g_h + (size_t)s1 * DD;
        float v00 = h0[lane],      v01 = h0[lane + 32];
        float v02 = h0[lane + 64], v03 = h0[lane + 96];
        float v10 = h1[lane],      v11 = h1[lane + 32];
        float v12 = h1[lane + 64], v13 = h1[lane + 96];
        acc0 = fmaf(e00, v00, acc0); acc1 = fmaf(e01, v01, acc1);
        acc2 = fmaf(e02, v02, acc2); acc3 = fmaf(e03, v03, acc3);
        acc0 = fmaf(e10, v10, acc0); acc1 = fmaf(e11, v11, acc1);
        acc2 = fmaf(e12, v12, acc2); acc3 = fmaf(e13, v13, acc3);
    }
    for (; p < end; p++) {
        int src = g_srcList[p];
        float ex = 0.f;
        if (lane < HH) {
            float l = g_as[src * HH + lane] + ad;
            l = l > 0.f ? l : 0.2f * l;
            ex = __expf(l);
            denom += ex;
        }
        float e0 = __shfl_sync(0xFFFFFFFFu, ex, hsel);
        float e1 = __shfl_sync(0xFFFFFFFFu, ex, 2 + hsel);
        float e2 = __shfl_sync(0xFFFFFFFFu, ex, 4 + hsel);
        float e3 = __shfl_sync(0xFFFFFFFFu, ex, 6 + hsel);
        const float* hp = g_h + (size_t)src * DD;
        acc0 = fmaf(e0, hp[lane],      acc0);
        acc1 = fmaf(e1, hp[lane + 32], acc1);
        acc2 = fmaf(e2, hp[lane + 64], acc2);
        acc3 = fmaf(e3, hp[lane + 96], acc3);
    }

    float dinv = (lane < HH) ? 1.f / (denom + 1e-16f) : 0.f;
    float d0 = __shfl_sync(0xFFFFFFFFu, dinv, hsel);
    float d1 = __shfl_sync(0xFFFFFFFFu, dinv, 2 + hsel);
    float d2 = __shfl_sync(0xFFFFFFFFu, dinv, 4 + hsel);
    float d3 = __shfl_sync(0xFFFFFFFFu, dinv, 6 + hsel);

    float* op = out + (size_t)n * DD;
    op[lane]      = acc0 * d0 + bias[lane];
    op[lane + 32] = acc1 * d1 + bias[lane + 32];
    op[lane + 64] = acc2 * d2 + bias[lane + 64];
    op[lane + 96] = acc3 * d3 + bias[lane + 96];

    if (alphaOut) {
        for (int q = beg; q < end; q++) {
            if (lane < HH) {
                int src = g_srcList[q];
                int eid = g_eidList[q];
                float l = g_as[src * HH + lane] + ad;
                l = l > 0.f ? l : 0.2f * l;
                alphaOut[(size_t)eid * HH + lane] = __expf(l) * dinv;
            }
        }
    }
}

// ---------------- optional ei output section -----------------------------------
__global__ void k_ei_f32(const void* __restrict__ ei, float* __restrict__ o) {
    int tid = blockIdx.x * blockDim.x + threadIdx.x;
    if (tid >= 2 * ETOT) return;
    int row = tid / ETOT;
    int i = tid - row * ETOT;
    long long v;
    if (i < EE) {
        v = g_is64 ? ((const long long*)ei)[(size_t)row * EE + i]
                   : (long long)((const int*)ei)[(size_t)row * EE + i];
    } else {
        v = (long long)(i - EE);
    }
    o[tid] = (float)v;
}

__global__ void k_ei_i64(const void* __restrict__ ei, long long* __restrict__ o) {
    int tid = blockIdx.x * blockDim.x + threadIdx.x;
    if (tid >= 2 * ETOT) return;
    int row = tid / ETOT;
    int i = tid - row * ETOT;
    long long v;
    if (i < EE) {
        v = g_is64 ? ((const long long*)ei)[(size_t)row * EE + i]
                   : (long long)((const int*)ei)[(size_t)row * EE + i];
    } else {
        v = (long long)(i - EE);
    }
    o[tid] = v;
}

// ---------------- launch --------------------------------------------------------
extern "C" void kernel_launch(void* const* d_in, const int* in_sizes, int n_in,
                              void* d_out, int out_size) {
    const float* x       = (const float*)d_in[0];
    const void*  ei      = d_in[1];
    const float* W       = (const float*)d_in[2];
    const float* att_src = (const float*)d_in[3];
    const float* att_dst = (const float*)d_in[4];
    const float* bias    = (const float*)d_in[5];
    float* out = (float*)d_out;

    const int OUTN = NN * DD;        // 12,800,000
    const int EIN  = 2 * ETOT;       //  1,800,000
    const int ALPH = ETOT * HH;      //  7,200,000

    float* alphaOut = nullptr;
    int    eiMode   = 0;             // 0 none, 1 float32, 2 int64
    if (out_size == OUTN + ALPH) {
        alphaOut = out + OUTN;
    } else if (out_size == OUTN + EIN + ALPH) {
        eiMode = 1;
        alphaOut = out + OUTN + EIN;
    } else if (out_size == OUTN + 2 * EIN + ALPH) {
        eiMode = 2;
        alphaOut = out + OUTN + 2 * EIN;
    }

    k_detect<<<1, 1>>>(ei);
    k_cnt_init<<<NB, 256>>>();
    k_hist<<<(EE + 255) / 256, 256>>>(ei);
    k_gemm<<<(NN + 127) / 128, 256>>>(x, W, att_src, att_dst);   // slot 4: profiled
    k_scan1<<<NB, 256>>>();
    k_scan2<<<1, 512>>>();
    k_scan3<<<NB, 256>>>();
    k_fill<<<(ETOT + 255) / 256, 256>>>(ei);
    k_agg<<<(NN * 32 + 255) / 256, 256>>>(out, alphaOut, bias);
    if (eiMode == 1) {
        k_ei_f32<<<(2 * ETOT + 255) / 256, 256>>>(ei, out + OUTN);
    } else if (eiMode == 2) {
        k_ei_i64<<<(2 * ETOT + 255) / 256, 256>>>(ei, (long long*)(out + OUTN));
    }
}